// round 1
// baseline (speedup 1.0000x reference)
#include <cuda_runtime.h>
#include <cstdint>

#define NN    50000
#define EE    800000
#define INF   500
#define HDIM  128
#define CDIM  40
#define KSTEPS 10

// Scratch (static __device__ allocations — allowed; ~84 MB)
__device__ float g_x0[(size_t)NN * HDIM];
__device__ float g_x1[(size_t)NN * HDIM];
__device__ float g_hidden[(size_t)NN * HDIM];
__device__ int   g_rowptr[NN + 1];
__device__ int   g_count[NN];
__device__ int   g_cursor[NN];
__device__ int   g_srcs[EE];
__device__ float g_norms[EE];

// ---------------------------------------------------------------------------
// CSR build
// ---------------------------------------------------------------------------
__global__ void zero_count_kernel() {
    int i = blockIdx.x * blockDim.x + threadIdx.x;
    if (i < NN) g_count[i] = 0;
}

__global__ void hist_kernel(const int* __restrict__ edge_index) {
    int e = blockIdx.x * blockDim.x + threadIdx.x;
    if (e < EE) {
        int d = edge_index[EE + e];  // dst row
        atomicAdd(&g_count[d], 1);
    }
}

// single-block exclusive scan of g_count -> g_rowptr (and g_cursor copy)
__global__ void scan_kernel() {
    __shared__ int buf[1024];
    int tid = threadIdx.x;
    int running = 0;
    for (int base = 0; base < NN; base += 1024) {
        int i = base + tid;
        int v = (i < NN) ? g_count[i] : 0;
        buf[tid] = v;
        __syncthreads();
        // Hillis-Steele inclusive scan
        for (int off = 1; off < 1024; off <<= 1) {
            int t = (tid >= off) ? buf[tid - off] : 0;
            __syncthreads();
            buf[tid] += t;
            __syncthreads();
        }
        int incl = buf[tid];
        int excl = incl - v;
        if (i < NN) {
            g_rowptr[i] = running + excl;
            g_cursor[i] = running + excl;
        }
        int chunk_total = buf[1023];
        __syncthreads();
        running += chunk_total;
    }
    if (tid == 0) g_rowptr[NN] = running;
}

__global__ void scatter_kernel(const int* __restrict__ edge_index,
                               const float* __restrict__ norm) {
    int e = blockIdx.x * blockDim.x + threadIdx.x;
    if (e < EE) {
        int s = edge_index[e];
        int d = edge_index[EE + e];
        int pos = atomicAdd(&g_cursor[d], 1);
        g_srcs[pos]  = s;
        g_norms[pos] = norm[e];
    }
}

// ---------------------------------------------------------------------------
// GEMM1: x0 = relu(feature @ W1 + b1); hidden = x0 * temp[:,0]
// BM=64, BN=128 (=HDIM), BK=16, 256 threads, thread tile 4x8
// ---------------------------------------------------------------------------
__global__ __launch_bounds__(256) void gemm1_kernel(
    const float* __restrict__ A,     // [NN, INF]
    const float* __restrict__ B,     // [INF, HDIM]
    const float* __restrict__ b1,    // [HDIM]
    const float* __restrict__ temp)  // [HDIM, KSTEPS+1]
{
    __shared__ float As[16][68];   // transposed, padded
    __shared__ float Bs[16][128];

    int t  = threadIdx.x;
    int tx = t & 15;   // col group (8 cols)
    int ty = t >> 4;   // row group (4 rows)
    int m0 = blockIdx.x * 64;

    float acc[4][8];
#pragma unroll
    for (int i = 0; i < 4; ++i)
#pragma unroll
        for (int j = 0; j < 8; ++j) acc[i][j] = 0.f;

    int ar = t >> 2;          // 0..63
    int ac = (t & 3) * 4;     // 0,4,8,12
    int br = t >> 5;          // 0..7
    int bc = (t & 31) * 4;    // 0..124

    for (int k0 = 0; k0 < INF; k0 += 16) {
        // ---- load A tile (64 x 16) -> As transposed ----
        {
            int grow = m0 + ar;
            float4 v = make_float4(0.f, 0.f, 0.f, 0.f);
            if (grow < NN) {
                int gcol = k0 + ac;
                if (gcol + 3 < INF) {
                    v = *(const float4*)(A + (size_t)grow * INF + gcol);
                } else {
                    float tmp[4] = {0.f, 0.f, 0.f, 0.f};
#pragma unroll
                    for (int j = 0; j < 4; ++j)
                        if (gcol + j < INF) tmp[j] = A[(size_t)grow * INF + gcol + j];
                    v = make_float4(tmp[0], tmp[1], tmp[2], tmp[3]);
                }
            }
            As[ac + 0][ar] = v.x;
            As[ac + 1][ar] = v.y;
            As[ac + 2][ar] = v.z;
            As[ac + 3][ar] = v.w;
        }
        // ---- load B tile (16 x 128) ----
#pragma unroll
        for (int r2 = 0; r2 < 2; ++r2) {
            int r  = br + r2 * 8;
            int gk = k0 + r;
            float4 v = make_float4(0.f, 0.f, 0.f, 0.f);
            if (gk < INF) v = *(const float4*)(B + (size_t)gk * HDIM + bc);
            *(float4*)&Bs[r][bc] = v;
        }
        __syncthreads();

#pragma unroll
        for (int kk = 0; kk < 16; ++kk) {
            float4 a4  = *(float4*)&As[kk][ty * 4];
            float4 b4a = *(float4*)&Bs[kk][tx * 8];
            float4 b4b = *(float4*)&Bs[kk][tx * 8 + 4];
            float a[4] = {a4.x, a4.y, a4.z, a4.w};
            float b[8] = {b4a.x, b4a.y, b4a.z, b4a.w, b4b.x, b4b.y, b4b.z, b4b.w};
#pragma unroll
            for (int i = 0; i < 4; ++i)
#pragma unroll
                for (int j = 0; j < 8; ++j)
                    acc[i][j] += a[i] * b[j];
        }
        __syncthreads();
    }

    // epilogue: bias + relu -> g_x0 ; * temp[:,0] -> g_hidden
#pragma unroll
    for (int i = 0; i < 4; ++i) {
        int n = m0 + ty * 4 + i;
        if (n >= NN) continue;
#pragma unroll
        for (int jj = 0; jj < 2; ++jj) {
            int c0 = tx * 8 + jj * 4;
            float v0 = fmaxf(acc[i][jj * 4 + 0] + b1[c0 + 0], 0.f);
            float v1 = fmaxf(acc[i][jj * 4 + 1] + b1[c0 + 1], 0.f);
            float v2 = fmaxf(acc[i][jj * 4 + 2] + b1[c0 + 2], 0.f);
            float v3 = fmaxf(acc[i][jj * 4 + 3] + b1[c0 + 3], 0.f);
            *(float4*)(g_x0 + (size_t)n * HDIM + c0) = make_float4(v0, v1, v2, v3);
            float h0 = v0 * temp[(c0 + 0) * (KSTEPS + 1)];
            float h1 = v1 * temp[(c0 + 1) * (KSTEPS + 1)];
            float h2 = v2 * temp[(c0 + 2) * (KSTEPS + 1)];
            float h3 = v3 * temp[(c0 + 3) * (KSTEPS + 1)];
            *(float4*)(g_hidden + (size_t)n * HDIM + c0) = make_float4(h0, h1, h2, h3);
        }
    }
}

// ---------------------------------------------------------------------------
// Propagation step: warp per node, lane handles 4 channels (float4)
// xout[n] = sum_{e in-edges(n)} norm[e] * xin[src[e]]
// hidden[n] += temp[:,k] * xout[n]
// ---------------------------------------------------------------------------
__global__ __launch_bounds__(256) void prop_step_kernel(
    int flip, int kstep, const float* __restrict__ temp)
{
    const float* __restrict__ xin  = flip ? g_x1 : g_x0;
    float* __restrict__       xout = flip ? g_x0 : g_x1;

    int w    = (blockIdx.x * blockDim.x + threadIdx.x) >> 5;
    int lane = threadIdx.x & 31;
    if (w >= NN) return;

    int beg = g_rowptr[w];
    int end = g_rowptr[w + 1];

    float ax = 0.f, ay = 0.f, az = 0.f, aw = 0.f;
    const float4* xin4 = (const float4*)xin;

#pragma unroll 4
    for (int e = beg; e < end; ++e) {
        int   ss = __ldg(&g_srcs[e]);     // uniform broadcast load
        float ww = __ldg(&g_norms[e]);
        float4 v = __ldg(xin4 + ((size_t)ss * 32 + lane));
        ax += ww * v.x;
        ay += ww * v.y;
        az += ww * v.z;
        aw += ww * v.w;
    }

    ((float4*)xout)[(size_t)w * 32 + lane] = make_float4(ax, ay, az, aw);

    int h0 = lane * 4;
    float g0 = temp[(h0 + 0) * (KSTEPS + 1) + kstep];
    float g1 = temp[(h0 + 1) * (KSTEPS + 1) + kstep];
    float g2 = temp[(h0 + 2) * (KSTEPS + 1) + kstep];
    float g3 = temp[(h0 + 3) * (KSTEPS + 1) + kstep];

    float4 hv = ((float4*)g_hidden)[(size_t)w * 32 + lane];
    hv.x += g0 * ax;
    hv.y += g1 * ay;
    hv.z += g2 * az;
    hv.w += g3 * aw;
    ((float4*)g_hidden)[(size_t)w * 32 + lane] = hv;
}

// ---------------------------------------------------------------------------
// GEMM2: out = hidden @ W2 + b2   (thread per node, acc[40] in registers)
// ---------------------------------------------------------------------------
__global__ __launch_bounds__(256) void gemm2_kernel(
    const float* __restrict__ W2,   // [HDIM, CDIM]
    const float* __restrict__ b2,   // [CDIM]
    float* __restrict__ out)        // [NN, CDIM]
{
    __shared__ float sW[HDIM * CDIM];
    __shared__ float sb[CDIM];
    for (int i = threadIdx.x; i < HDIM * CDIM; i += blockDim.x) sW[i] = W2[i];
    if (threadIdx.x < CDIM) sb[threadIdx.x] = b2[threadIdx.x];
    __syncthreads();

    int n = blockIdx.x * blockDim.x + threadIdx.x;
    if (n >= NN) return;

    float acc[CDIM];
#pragma unroll
    for (int c = 0; c < CDIM; ++c) acc[c] = sb[c];

    const float4* hrow = (const float4*)(g_hidden + (size_t)n * HDIM);
#pragma unroll 4
    for (int h4 = 0; h4 < HDIM / 4; ++h4) {
        float4 hv = __ldg(hrow + h4);
        const float* w0 = &sW[(h4 * 4 + 0) * CDIM];
        const float* w1 = &sW[(h4 * 4 + 1) * CDIM];
        const float* w2 = &sW[(h4 * 4 + 2) * CDIM];
        const float* w3 = &sW[(h4 * 4 + 3) * CDIM];
#pragma unroll
        for (int c = 0; c < CDIM; ++c) {
            acc[c] += hv.x * w0[c];
            acc[c] += hv.y * w1[c];
            acc[c] += hv.z * w2[c];
            acc[c] += hv.w * w3[c];
        }
    }

    float4* o = (float4*)(out + (size_t)n * CDIM);
#pragma unroll
    for (int c4 = 0; c4 < CDIM / 4; ++c4)
        o[c4] = make_float4(acc[c4 * 4], acc[c4 * 4 + 1], acc[c4 * 4 + 2], acc[c4 * 4 + 3]);
}

// ---------------------------------------------------------------------------
extern "C" void kernel_launch(void* const* d_in, const int* in_sizes, int n_in,
                              void* d_out, int out_size)
{
    const float* feature    = (const float*)d_in[0];
    const float* W1         = (const float*)d_in[1];
    const float* b1         = (const float*)d_in[2];
    const float* W2         = (const float*)d_in[3];
    const float* b2         = (const float*)d_in[4];
    const float* temp       = (const float*)d_in[5];
    const float* norm       = (const float*)d_in[6];
    const int*   edge_index = (const int*)d_in[7];
    float* out = (float*)d_out;

    // CSR build
    zero_count_kernel<<<(NN + 255) / 256, 256>>>();
    hist_kernel<<<(EE + 255) / 256, 256>>>(edge_index);
    scan_kernel<<<1, 1024>>>();
    scatter_kernel<<<(EE + 255) / 256, 256>>>(edge_index, norm);

    // lin1 + relu + hidden init
    gemm1_kernel<<<(NN + 63) / 64, 256>>>(feature, W1, b1, temp);

    // K propagation steps
    int total_warps = NN;
    int prop_blocks = (total_warps * 32 + 255) / 256;
    for (int k = 1; k <= KSTEPS; ++k) {
        prop_step_kernel<<<prop_blocks, 256>>>((k - 1) & 1, k, temp);
    }

    // lin2
    gemm2_kernel<<<(NN + 255) / 256, 256>>>(W2, b2, out);
}

// round 2
// speedup vs baseline: 1.1298x; 1.1298x over previous
#include <cuda_runtime.h>
#include <cuda_fp16.h>
#include <cuda_bf16.h>
#include <cstdint>

#define NN    50000
#define EE    800000
#define INF   500
#define HDIM  128
#define CDIM  40
#define KSTEPS 10

// Scratch (static __device__ allocations)
__device__ __half g_xh0[(size_t)NN * HDIM];
__device__ __half g_xh1[(size_t)NN * HDIM];
__device__ float  g_hidden[(size_t)NN * HDIM];
__device__ int    g_rowptr[NN + 1];
__device__ int    g_count[NN];
__device__ int    g_cursor[NN];
__device__ int    g_srcs[EE];
__device__ float  g_norms[EE];   // norm/16 (per-step rescale folded in)

// ---------------------------------------------------------------------------
// CSR build
// ---------------------------------------------------------------------------
__global__ void zero_count_kernel() {
    int i = blockIdx.x * blockDim.x + threadIdx.x;
    if (i < NN) g_count[i] = 0;
}

__global__ void hist_kernel(const int* __restrict__ edge_index) {
    int e = blockIdx.x * blockDim.x + threadIdx.x;
    if (e < EE) {
        int d = edge_index[EE + e];
        atomicAdd(&g_count[d], 1);
    }
}

// single-block exclusive scan (warp-shuffle based)
__global__ void scan_kernel() {
    __shared__ int wsum[32];
    __shared__ int sbase;
    int tid = threadIdx.x, lane = tid & 31, wid = tid >> 5;
    if (tid == 0) sbase = 0;
    __syncthreads();
    for (int base = 0; base < NN; base += 1024) {
        int i = base + tid;
        int v = (i < NN) ? g_count[i] : 0;
        int incl = v;
#pragma unroll
        for (int off = 1; off < 32; off <<= 1) {
            int t = __shfl_up_sync(0xffffffffu, incl, off);
            if (lane >= off) incl += t;
        }
        if (lane == 31) wsum[wid] = incl;
        __syncthreads();
        if (wid == 0) {
            int s = wsum[lane];
            int si = s;
#pragma unroll
            for (int off = 1; off < 32; off <<= 1) {
                int t = __shfl_up_sync(0xffffffffu, si, off);
                if (lane >= off) si += t;
            }
            wsum[lane] = si - s;  // exclusive
        }
        __syncthreads();
        int excl = incl - v + wsum[wid] + sbase;
        if (i < NN) { g_rowptr[i] = excl; g_cursor[i] = excl; }
        __syncthreads();
        if (tid == 1023) sbase = excl + v;  // global inclusive through chunk end
        __syncthreads();
    }
    if (threadIdx.x == 0) g_rowptr[NN] = sbase;
}

__global__ void scatter_kernel(const int* __restrict__ edge_index,
                               const float* __restrict__ norm) {
    int e = blockIdx.x * blockDim.x + threadIdx.x;
    if (e < EE) {
        int s = edge_index[e];
        int d = edge_index[EE + e];
        int pos = atomicAdd(&g_cursor[d], 1);
        g_srcs[pos]  = s;
        g_norms[pos] = norm[e] * 0.0625f;   // fold 1/16 per-step rescale
    }
}

// ---------------------------------------------------------------------------
// GEMM1 (tensor cores, split-bf16 3-pass):
//   x = relu(feature @ W1 + b1)  -> g_xh0 (fp16), g_hidden = x * temp[:,0]
// CTA tile 128x128, BK=32, 8 warps (4x2), warp tile 32x64 via m16n8k16.
// ---------------------------------------------------------------------------
__device__ __forceinline__ void mma16816(float c[4], const uint32_t a[4],
                                         uint32_t b0, uint32_t b1) {
    asm volatile(
        "mma.sync.aligned.m16n8k16.row.col.f32.bf16.bf16.f32 "
        "{%0,%1,%2,%3}, {%4,%5,%6,%7}, {%8,%9}, {%0,%1,%2,%3};"
        : "+f"(c[0]), "+f"(c[1]), "+f"(c[2]), "+f"(c[3])
        : "r"(a[0]), "r"(a[1]), "r"(a[2]), "r"(a[3]), "r"(b0), "r"(b1));
}

__global__ __launch_bounds__(256) void gemm1_tc_kernel(
    const float* __restrict__ A,     // [NN, INF]
    const float* __restrict__ B,     // [INF, HDIM]
    const float* __restrict__ b1,    // [HDIM]
    const float* __restrict__ temp)  // [HDIM, KSTEPS+1]
{
    __shared__ __nv_bfloat16 Ah[128][40];
    __shared__ __nv_bfloat16 Al[128][40];
    __shared__ __nv_bfloat16 Bh[128][40];   // transposed: [n][k]
    __shared__ __nv_bfloat16 Bl[128][40];
    __shared__ float sBias[HDIM];
    __shared__ float sG0[HDIM];

    int tid = threadIdx.x;
    int m0 = blockIdx.x * 128;

    if (tid < HDIM) {
        sBias[tid] = b1[tid];
        sG0[tid]   = temp[tid * (KSTEPS + 1)];
    }

    int lane = tid & 31, wid = tid >> 5;
    int g = lane >> 2, tig = lane & 3;
    int wr = wid >> 1, wc = wid & 1;
    int mBase = wr * 32, nBase = wc * 64;

    float c[2][8][4];
#pragma unroll
    for (int mt = 0; mt < 2; ++mt)
#pragma unroll
        for (int nt = 0; nt < 8; ++nt)
#pragma unroll
            for (int q = 0; q < 4; ++q) c[mt][nt][q] = 0.f;

    for (int k0 = 0; k0 < 512; k0 += 32) {
        // ---- A tile: 128x32 fp32 -> split bf16 ----
#pragma unroll
        for (int i = 0; i < 4; ++i) {
            int idx = tid + 256 * i;     // 0..1023 float4 slots
            int row = idx >> 3;
            int c4  = idx & 7;
            int grow = m0 + row;
            int gk = k0 + c4 * 4;
            float4 v = make_float4(0.f, 0.f, 0.f, 0.f);
            if (grow < NN && gk < INF)
                v = *(const float4*)(A + (size_t)grow * INF + gk);
            float vv[4] = {v.x, v.y, v.z, v.w};
#pragma unroll
            for (int j = 0; j < 4; ++j) {
                __nv_bfloat16 hi = __float2bfloat16_rn(vv[j]);
                __nv_bfloat16 lo = __float2bfloat16_rn(vv[j] - __bfloat162float(hi));
                Ah[row][c4 * 4 + j] = hi;
                Al[row][c4 * 4 + j] = lo;
            }
        }
        // ---- B tile: 32x128 fp32 -> split bf16, transposed ----
#pragma unroll
        for (int i = 0; i < 4; ++i) {
            int idx = tid + 256 * i;
            int krow = idx >> 5;
            int c4   = idx & 31;
            int gk = k0 + krow;
            int n0 = c4 * 4;
            float4 v = make_float4(0.f, 0.f, 0.f, 0.f);
            if (gk < INF)
                v = *(const float4*)(B + (size_t)gk * HDIM + n0);
            float vv[4] = {v.x, v.y, v.z, v.w};
#pragma unroll
            for (int j = 0; j < 4; ++j) {
                __nv_bfloat16 hi = __float2bfloat16_rn(vv[j]);
                __nv_bfloat16 lo = __float2bfloat16_rn(vv[j] - __bfloat162float(hi));
                Bh[n0 + j][krow] = hi;
                Bl[n0 + j][krow] = lo;
            }
        }
        __syncthreads();

#pragma unroll
        for (int kk = 0; kk < 32; kk += 16) {
            uint32_t ah[2][4], al[2][4];
            int kc = kk + 2 * tig;
#pragma unroll
            for (int mt = 0; mt < 2; ++mt) {
                int r0 = mBase + mt * 16 + g;
                ah[mt][0] = *(const uint32_t*)&Ah[r0][kc];
                ah[mt][1] = *(const uint32_t*)&Ah[r0 + 8][kc];
                ah[mt][2] = *(const uint32_t*)&Ah[r0][kc + 8];
                ah[mt][3] = *(const uint32_t*)&Ah[r0 + 8][kc + 8];
                al[mt][0] = *(const uint32_t*)&Al[r0][kc];
                al[mt][1] = *(const uint32_t*)&Al[r0 + 8][kc];
                al[mt][2] = *(const uint32_t*)&Al[r0][kc + 8];
                al[mt][3] = *(const uint32_t*)&Al[r0 + 8][kc + 8];
            }
#pragma unroll
            for (int nt = 0; nt < 8; ++nt) {
                int nn = nBase + nt * 8 + g;
                uint32_t bh0 = *(const uint32_t*)&Bh[nn][kc];
                uint32_t bh1 = *(const uint32_t*)&Bh[nn][kc + 8];
                uint32_t bl0 = *(const uint32_t*)&Bl[nn][kc];
                uint32_t bl1 = *(const uint32_t*)&Bl[nn][kc + 8];
#pragma unroll
                for (int mt = 0; mt < 2; ++mt) {
                    mma16816(c[mt][nt], ah[mt], bh0, bh1);
                    mma16816(c[mt][nt], ah[mt], bl0, bl1);
                    mma16816(c[mt][nt], al[mt], bh0, bh1);
                }
            }
        }
        __syncthreads();
    }

    // ---- epilogue: bias+relu -> fp16 x0 ; *gamma0 -> fp32 hidden ----
#pragma unroll
    for (int mt = 0; mt < 2; ++mt) {
#pragma unroll
        for (int nt = 0; nt < 8; ++nt) {
            int col = nBase + nt * 8 + 2 * tig;
            float bb0 = sBias[col], bb1 = sBias[col + 1];
            float g0 = sG0[col], g1 = sG0[col + 1];
#pragma unroll
            for (int rh = 0; rh < 2; ++rh) {
                int row = m0 + mBase + mt * 16 + g + rh * 8;
                if (row >= NN) continue;
                float v0 = fmaxf(c[mt][nt][rh * 2 + 0] + bb0, 0.f);
                float v1 = fmaxf(c[mt][nt][rh * 2 + 1] + bb1, 0.f);
                *(__half2*)(g_xh0 + (size_t)row * HDIM + col) =
                    __floats2half2_rn(v0, v1);
                *(float2*)(g_hidden + (size_t)row * HDIM + col) =
                    make_float2(v0 * g0, v1 * g1);
            }
        }
    }
}

// ---------------------------------------------------------------------------
// Propagation step (fp16 x, fp32 accumulate): warp per node, lane = 4 channels
// stored_k = x_k / 16^k ; norms pre-scaled by 1/16 ; gamma scaled by 16^k
// ---------------------------------------------------------------------------
__global__ __launch_bounds__(256) void prop_step_kernel(
    int flip, int kstep, float gscale, const float* __restrict__ temp)
{
    const __half* __restrict__ xin  = flip ? g_xh1 : g_xh0;
    __half* __restrict__       xout = flip ? g_xh0 : g_xh1;

    int w    = (blockIdx.x * blockDim.x + threadIdx.x) >> 5;
    int lane = threadIdx.x & 31;
    if (w >= NN) return;

    int beg = g_rowptr[w];
    int end = g_rowptr[w + 1];
    int deg = end - beg;

    float ax = 0.f, ay = 0.f, az = 0.f, aw = 0.f;
    const uint2* xin4 = (const uint2*)xin;

    for (int t0 = 0; t0 < deg; t0 += 32) {
        int idx = t0 + lane;
        int   s_l = 0; float w_l = 0.f;
        if (idx < deg) {
            s_l = __ldg(&g_srcs[beg + idx]);
            w_l = __ldg(&g_norms[beg + idx]);
        }
        int cnt = min(32, deg - t0);
#pragma unroll 4
        for (int j = 0; j < cnt; ++j) {
            int   ss = __shfl_sync(0xffffffffu, s_l, j);
            float ww = __shfl_sync(0xffffffffu, w_l, j);
            uint2 u = __ldg(xin4 + ((size_t)ss * 32 + lane));
            float2 f0 = __half22float2(*(__half2*)&u.x);
            float2 f1 = __half22float2(*(__half2*)&u.y);
            ax += ww * f0.x;
            ay += ww * f0.y;
            az += ww * f1.x;
            aw += ww * f1.y;
        }
    }

    uint2 o;
    *(__half2*)&o.x = __floats2half2_rn(ax, ay);
    *(__half2*)&o.y = __floats2half2_rn(az, aw);
    ((uint2*)xout)[(size_t)w * 32 + lane] = o;

    int h0 = lane * 4;
    float g0 = temp[(h0 + 0) * (KSTEPS + 1) + kstep] * gscale;
    float g1 = temp[(h0 + 1) * (KSTEPS + 1) + kstep] * gscale;
    float g2 = temp[(h0 + 2) * (KSTEPS + 1) + kstep] * gscale;
    float g3 = temp[(h0 + 3) * (KSTEPS + 1) + kstep] * gscale;

    float4 hv = ((float4*)g_hidden)[(size_t)w * 32 + lane];
    hv.x += g0 * ax;
    hv.y += g1 * ay;
    hv.z += g2 * az;
    hv.w += g3 * aw;
    ((float4*)g_hidden)[(size_t)w * 32 + lane] = hv;
}

// ---------------------------------------------------------------------------
// GEMM2: out = hidden @ W2 + b2   (thread per node, acc[40] in registers)
// ---------------------------------------------------------------------------
__global__ __launch_bounds__(256) void gemm2_kernel(
    const float* __restrict__ W2,   // [HDIM, CDIM]
    const float* __restrict__ b2,   // [CDIM]
    float* __restrict__ out)        // [NN, CDIM]
{
    __shared__ float sW[HDIM * CDIM];
    __shared__ float sb[CDIM];
    for (int i = threadIdx.x; i < HDIM * CDIM; i += blockDim.x) sW[i] = W2[i];
    if (threadIdx.x < CDIM) sb[threadIdx.x] = b2[threadIdx.x];
    __syncthreads();

    int n = blockIdx.x * blockDim.x + threadIdx.x;
    if (n >= NN) return;

    float acc[CDIM];
#pragma unroll
    for (int c = 0; c < CDIM; ++c) acc[c] = sb[c];

    const float4* hrow = (const float4*)(g_hidden + (size_t)n * HDIM);
#pragma unroll 4
    for (int h4 = 0; h4 < HDIM / 4; ++h4) {
        float4 hv = __ldg(hrow + h4);
        const float* w0 = &sW[(h4 * 4 + 0) * CDIM];
        const float* w1 = &sW[(h4 * 4 + 1) * CDIM];
        const float* w2 = &sW[(h4 * 4 + 2) * CDIM];
        const float* w3 = &sW[(h4 * 4 + 3) * CDIM];
#pragma unroll
        for (int c = 0; c < CDIM; ++c) {
            acc[c] += hv.x * w0[c];
            acc[c] += hv.y * w1[c];
            acc[c] += hv.z * w2[c];
            acc[c] += hv.w * w3[c];
        }
    }

    float4* o = (float4*)(out + (size_t)n * CDIM);
#pragma unroll
    for (int c4 = 0; c4 < CDIM / 4; ++c4)
        o[c4] = make_float4(acc[c4 * 4], acc[c4 * 4 + 1], acc[c4 * 4 + 2], acc[c4 * 4 + 3]);
}

// ---------------------------------------------------------------------------
extern "C" void kernel_launch(void* const* d_in, const int* in_sizes, int n_in,
                              void* d_out, int out_size)
{
    const float* feature    = (const float*)d_in[0];
    const float* W1         = (const float*)d_in[1];
    const float* b1         = (const float*)d_in[2];
    const float* W2         = (const float*)d_in[3];
    const float* b2         = (const float*)d_in[4];
    const float* temp       = (const float*)d_in[5];
    const float* norm       = (const float*)d_in[6];
    const int*   edge_index = (const int*)d_in[7];
    float* out = (float*)d_out;

    // CSR build
    zero_count_kernel<<<(NN + 255) / 256, 256>>>();
    hist_kernel<<<(EE + 255) / 256, 256>>>(edge_index);
    scan_kernel<<<1, 1024>>>();
    scatter_kernel<<<(EE + 255) / 256, 256>>>(edge_index, norm);

    // lin1 + relu + hidden init (tensor cores, split-bf16)
    gemm1_tc_kernel<<<(NN + 127) / 128, 256>>>(feature, W1, b1, temp);

    // K propagation steps (fp16 x with 16^-k rescale)
    int prop_blocks = (NN * 32 + 255) / 256;
    float gs = 1.0f;
    for (int k = 1; k <= KSTEPS; ++k) {
        gs *= 16.0f;
        prop_step_kernel<<<prop_blocks, 256>>>((k - 1) & 1, k, gs, temp);
    }

    // lin2
    gemm2_kernel<<<(NN + 255) / 256, 256>>>(W2, b2, out);
}

// round 3
// speedup vs baseline: 1.5706x; 1.3902x over previous
#include <cuda_runtime.h>
#include <cuda_fp16.h>
#include <cuda_bf16.h>
#include <cstdint>

#define NN    50000
#define EE    800000
#define INF   500
#define HDIM  128
#define CDIM  40
#define KSTEPS 10

// Scratch (static __device__ allocations)
__device__ __half g_xh0[(size_t)NN * HDIM];
__device__ __half g_xh1[(size_t)NN * HDIM];
__device__ float  g_hidden[(size_t)NN * HDIM];
__device__ int    g_rowptr[NN + 1];
__device__ int    g_count[NN];
__device__ int    g_cursor[NN];
__device__ int    g_srcs[EE];
__device__ float  g_norms[EE];   // norm/16 (per-step rescale folded in)

// ---------------------------------------------------------------------------
// CSR build
// ---------------------------------------------------------------------------
__global__ void zero_count_kernel() {
    int i = blockIdx.x * blockDim.x + threadIdx.x;
    if (i < NN) g_count[i] = 0;
}

__global__ void hist_kernel(const int* __restrict__ edge_index) {
    int e = blockIdx.x * blockDim.x + threadIdx.x;
    if (e < EE) {
        int d = edge_index[EE + e];
        atomicAdd(&g_count[d], 1);
    }
}

// single-block exclusive scan (warp-shuffle based)
__global__ void scan_kernel() {
    __shared__ int wsum[32];
    __shared__ int sbase;
    int tid = threadIdx.x, lane = tid & 31, wid = tid >> 5;
    if (tid == 0) sbase = 0;
    __syncthreads();
    for (int base = 0; base < NN; base += 1024) {
        int i = base + tid;
        int v = (i < NN) ? g_count[i] : 0;
        int incl = v;
#pragma unroll
        for (int off = 1; off < 32; off <<= 1) {
            int t = __shfl_up_sync(0xffffffffu, incl, off);
            if (lane >= off) incl += t;
        }
        if (lane == 31) wsum[wid] = incl;
        __syncthreads();
        if (wid == 0) {
            int s = wsum[lane];
            int si = s;
#pragma unroll
            for (int off = 1; off < 32; off <<= 1) {
                int t = __shfl_up_sync(0xffffffffu, si, off);
                if (lane >= off) si += t;
            }
            wsum[lane] = si - s;  // exclusive
        }
        __syncthreads();
        int excl = incl - v + wsum[wid] + sbase;
        if (i < NN) { g_rowptr[i] = excl; g_cursor[i] = excl; }
        __syncthreads();
        if (tid == 1023) sbase = excl + v;
        __syncthreads();
    }
    if (threadIdx.x == 0) g_rowptr[NN] = sbase;
}

__global__ void scatter_kernel(const int* __restrict__ edge_index,
                               const float* __restrict__ norm) {
    int e = blockIdx.x * blockDim.x + threadIdx.x;
    if (e < EE) {
        int s = edge_index[e];
        int d = edge_index[EE + e];
        int pos = atomicAdd(&g_cursor[d], 1);
        g_srcs[pos]  = s;
        g_norms[pos] = norm[e] * 0.0625f;
    }
}

// ---------------------------------------------------------------------------
// GEMM1 (tensor cores, split-bf16 3-pass, ldmatrix + STS.64):
//   x = relu(feature @ W1 + b1)  -> g_xh0 (fp16), g_hidden = x * temp[:,0]
// CTA 128x128, BK=32, 8 warps (4x2), warp tile 32x64 via m16n8k16.
// ---------------------------------------------------------------------------
__device__ __forceinline__ void mma16816(float c[4], const uint32_t a[4],
                                         uint32_t b0, uint32_t b1) {
    asm volatile(
        "mma.sync.aligned.m16n8k16.row.col.f32.bf16.bf16.f32 "
        "{%0,%1,%2,%3}, {%4,%5,%6,%7}, {%8,%9}, {%0,%1,%2,%3};"
        : "+f"(c[0]), "+f"(c[1]), "+f"(c[2]), "+f"(c[3])
        : "r"(a[0]), "r"(a[1]), "r"(a[2]), "r"(a[3]), "r"(b0), "r"(b1));
}

__device__ __forceinline__ void ldsm4(uint32_t& r0, uint32_t& r1,
                                      uint32_t& r2, uint32_t& r3, uint32_t addr) {
    asm volatile(
        "ldmatrix.sync.aligned.m8n8.x4.shared.b16 {%0,%1,%2,%3}, [%4];"
        : "=r"(r0), "=r"(r1), "=r"(r2), "=r"(r3) : "r"(addr));
}

__device__ __forceinline__ void split_bf16(float v, __nv_bfloat16& hi, __nv_bfloat16& lo) {
    hi = __float2bfloat16_rn(v);
    lo = __float2bfloat16_rn(v - __bfloat162float(hi));
}

#define PADC 40   // smem row length in bf16 (80 bytes) — LDSM conflict-free

__global__ __launch_bounds__(256) void gemm1_tc_kernel(
    const float* __restrict__ A,     // [NN, INF]
    const float* __restrict__ B,     // [INF, HDIM]
    const float* __restrict__ b1,    // [HDIM]
    const float* __restrict__ temp)  // [HDIM, KSTEPS+1]
{
    __shared__ __nv_bfloat16 Ah[128][PADC];
    __shared__ __nv_bfloat16 Al[128][PADC];
    __shared__ __nv_bfloat16 Bh[128][PADC];   // transposed: [n][k]
    __shared__ __nv_bfloat16 Bl[128][PADC];
    __shared__ float sBias[HDIM];
    __shared__ float sG0[HDIM];

    int tid = threadIdx.x;
    int m0 = blockIdx.x * 128;

    if (tid < HDIM) {
        sBias[tid] = b1[tid];
        sG0[tid]   = temp[tid * (KSTEPS + 1)];
    }

    int lane = tid & 31, wid = tid >> 5;
    int g = lane >> 2, tig = lane & 3;
    int wr = wid >> 1, wc = wid & 1;
    int mBase = wr * 32, nBase = wc * 64;

    // ldmatrix lane addresses (byte offsets within smem arrays)
    uint32_t ahBase = (uint32_t)__cvta_generic_to_shared(&Ah[0][0]);
    uint32_t alBase = (uint32_t)__cvta_generic_to_shared(&Al[0][0]);
    uint32_t bhBase = (uint32_t)__cvta_generic_to_shared(&Bh[0][0]);
    uint32_t blBase = (uint32_t)__cvta_generic_to_shared(&Bl[0][0]);

    int aRow = mBase + (lane & 7) + ((lane >> 3) & 1) * 8;
    uint32_t aOff = (uint32_t)(aRow * (PADC * 2) + ((lane >> 4) & 1) * 16);
    int bRow = nBase + (lane & 7) + ((lane >> 4) & 1) * 8;
    uint32_t bOff = (uint32_t)(bRow * (PADC * 2) + ((lane >> 3) & 1) * 16);

    float c[2][8][4];
#pragma unroll
    for (int mt = 0; mt < 2; ++mt)
#pragma unroll
        for (int nt = 0; nt < 8; ++nt)
#pragma unroll
            for (int q = 0; q < 4; ++q) c[mt][nt][q] = 0.f;

    for (int k0 = 0; k0 < 512; k0 += 32) {
        // ---- A tile: 128x32 fp32 -> split bf16, STS.64 ----
#pragma unroll
        for (int i = 0; i < 4; ++i) {
            int idx = tid + 256 * i;       // 1024 float4 slots
            int row = idx >> 3;
            int c4  = (idx & 7) * 4;       // k offset in tile
            int grow = m0 + row;
            int gk = k0 + c4;
            float4 v = make_float4(0.f, 0.f, 0.f, 0.f);
            if (grow < NN && gk + 4 <= INF)
                v = *(const float4*)(A + (size_t)grow * INF + gk);
            __nv_bfloat16 h[4], l[4];
            split_bf16(v.x, h[0], l[0]);
            split_bf16(v.y, h[1], l[1]);
            split_bf16(v.z, h[2], l[2]);
            split_bf16(v.w, h[3], l[3]);
            *(uint2*)&Ah[row][c4] = *(uint2*)h;
            *(uint2*)&Al[row][c4] = *(uint2*)l;
        }
        // ---- B tile: 32x128 fp32 -> split bf16, transposed, STS.64 ----
#pragma unroll
        for (int i = 0; i < 4; ++i) {
            int idx = tid + 256 * i;       // 1024 slots: (kr4, n)
            int n    = idx & 127;
            int kr4  = (idx >> 7) * 4;     // k offset in tile
            __nv_bfloat16 h[4], l[4];
#pragma unroll
            for (int j = 0; j < 4; ++j) {
                int gk = k0 + kr4 + j;
                float v = (gk < INF) ? __ldg(B + (size_t)gk * HDIM + n) : 0.f;
                split_bf16(v, h[j], l[j]);
            }
            *(uint2*)&Bh[n][kr4] = *(uint2*)h;
            *(uint2*)&Bl[n][kr4] = *(uint2*)l;
        }
        __syncthreads();

#pragma unroll
        for (int kk = 0; kk < 32; kk += 16) {
            uint32_t AH[2][4], AL[2][4];
#pragma unroll
            for (int mt = 0; mt < 2; ++mt) {
                uint32_t off = aOff + (uint32_t)(mt * 16 * PADC * 2 + kk * 2);
                ldsm4(AH[mt][0], AH[mt][1], AH[mt][2], AH[mt][3], ahBase + off);
                ldsm4(AL[mt][0], AL[mt][1], AL[mt][2], AL[mt][3], alBase + off);
            }
#pragma unroll
            for (int np = 0; np < 4; ++np) {
                uint32_t off = bOff + (uint32_t)(np * 16 * PADC * 2 + kk * 2);
                uint32_t BH[4], BL[4];
                ldsm4(BH[0], BH[1], BH[2], BH[3], bhBase + off);
                ldsm4(BL[0], BL[1], BL[2], BL[3], blBase + off);
#pragma unroll
                for (int mt = 0; mt < 2; ++mt) {
                    mma16816(c[mt][2 * np],     AH[mt], BH[0], BH[1]);
                    mma16816(c[mt][2 * np],     AH[mt], BL[0], BL[1]);
                    mma16816(c[mt][2 * np],     AL[mt], BH[0], BH[1]);
                    mma16816(c[mt][2 * np + 1], AH[mt], BH[2], BH[3]);
                    mma16816(c[mt][2 * np + 1], AH[mt], BL[2], BL[3]);
                    mma16816(c[mt][2 * np + 1], AL[mt], BH[2], BH[3]);
                }
            }
        }
        __syncthreads();
    }

    // ---- epilogue: bias+relu -> fp16 x0 ; *gamma0 -> fp32 hidden ----
#pragma unroll
    for (int mt = 0; mt < 2; ++mt) {
#pragma unroll
        for (int nt = 0; nt < 8; ++nt) {
            int col = nBase + nt * 8 + 2 * tig;
            float bb0 = sBias[col], bb1 = sBias[col + 1];
            float g0 = sG0[col], g1 = sG0[col + 1];
#pragma unroll
            for (int rh = 0; rh < 2; ++rh) {
                int row = m0 + mBase + mt * 16 + g + rh * 8;
                if (row >= NN) continue;
                float v0 = fmaxf(c[mt][nt][rh * 2 + 0] + bb0, 0.f);
                float v1 = fmaxf(c[mt][nt][rh * 2 + 1] + bb1, 0.f);
                *(__half2*)(g_xh0 + (size_t)row * HDIM + col) =
                    __floats2half2_rn(v0, v1);
                *(float2*)(g_hidden + (size_t)row * HDIM + col) =
                    make_float2(v0 * g0, v1 * g1);
            }
        }
    }
}

// ---------------------------------------------------------------------------
// Propagation step (fp16 x, fp32 accumulate): warp per node, lane = 4 channels
// stored_k = x_k / 16^k ; norms pre-scaled by 1/16 ; gamma scaled by 16^k
// ---------------------------------------------------------------------------
__global__ __launch_bounds__(256) void prop_step_kernel(
    int flip, int kstep, float gscale, const float* __restrict__ temp)
{
    const __half* __restrict__ xin  = flip ? g_xh1 : g_xh0;
    __half* __restrict__       xout = flip ? g_xh0 : g_xh1;

    int w    = (blockIdx.x * blockDim.x + threadIdx.x) >> 5;
    int lane = threadIdx.x & 31;
    if (w >= NN) return;

    int beg = g_rowptr[w];
    int end = g_rowptr[w + 1];

    float ax = 0.f, ay = 0.f, az = 0.f, aw = 0.f;
    const uint2* xin4 = (const uint2*)xin;

#pragma unroll 4
    for (int e = beg; e < end; ++e) {
        int   ss = __ldg(&g_srcs[e]);     // uniform broadcast load
        float ww = __ldg(&g_norms[e]);
        uint2 u = __ldg(xin4 + ((size_t)ss * 32 + lane));
        float2 f0 = __half22float2(*(__half2*)&u.x);
        float2 f1 = __half22float2(*(__half2*)&u.y);
        ax += ww * f0.x;
        ay += ww * f0.y;
        az += ww * f1.x;
        aw += ww * f1.y;
    }

    uint2 o;
    *(__half2*)&o.x = __floats2half2_rn(ax, ay);
    *(__half2*)&o.y = __floats2half2_rn(az, aw);
    ((uint2*)xout)[(size_t)w * 32 + lane] = o;

    int h0 = lane * 4;
    float g0 = temp[(h0 + 0) * (KSTEPS + 1) + kstep] * gscale;
    float g1 = temp[(h0 + 1) * (KSTEPS + 1) + kstep] * gscale;
    float g2 = temp[(h0 + 2) * (KSTEPS + 1) + kstep] * gscale;
    float g3 = temp[(h0 + 3) * (KSTEPS + 1) + kstep] * gscale;

    float4 hv = ((float4*)g_hidden)[(size_t)w * 32 + lane];
    hv.x += g0 * ax;
    hv.y += g1 * ay;
    hv.z += g2 * az;
    hv.w += g3 * aw;
    ((float4*)g_hidden)[(size_t)w * 32 + lane] = hv;
}

// ---------------------------------------------------------------------------
// GEMM2: out = hidden @ W2 + b2   (thread per node, acc[40] in registers)
// ---------------------------------------------------------------------------
__global__ __launch_bounds__(256) void gemm2_kernel(
    const float* __restrict__ W2,   // [HDIM, CDIM]
    const float* __restrict__ b2,   // [CDIM]
    float* __restrict__ out)        // [NN, CDIM]
{
    __shared__ float sW[HDIM * CDIM];
    __shared__ float sb[CDIM];
    for (int i = threadIdx.x; i < HDIM * CDIM; i += blockDim.x) sW[i] = W2[i];
    if (threadIdx.x < CDIM) sb[threadIdx.x] = b2[threadIdx.x];
    __syncthreads();

    int n = blockIdx.x * blockDim.x + threadIdx.x;
    if (n >= NN) return;

    float acc[CDIM];
#pragma unroll
    for (int c = 0; c < CDIM; ++c) acc[c] = sb[c];

    const float4* hrow = (const float4*)(g_hidden + (size_t)n * HDIM);
#pragma unroll 4
    for (int h4 = 0; h4 < HDIM / 4; ++h4) {
        float4 hv = __ldg(hrow + h4);
        const float* w0 = &sW[(h4 * 4 + 0) * CDIM];
        const float* w1 = &sW[(h4 * 4 + 1) * CDIM];
        const float* w2 = &sW[(h4 * 4 + 2) * CDIM];
        const float* w3 = &sW[(h4 * 4 + 3) * CDIM];
#pragma unroll
        for (int c = 0; c < CDIM; ++c) {
            acc[c] += hv.x * w0[c];
            acc[c] += hv.y * w1[c];
            acc[c] += hv.z * w2[c];
            acc[c] += hv.w * w3[c];
        }
    }

    float4* o = (float4*)(out + (size_t)n * CDIM);
#pragma unroll
    for (int c4 = 0; c4 < CDIM / 4; ++c4)
        o[c4] = make_float4(acc[c4 * 4], acc[c4 * 4 + 1], acc[c4 * 4 + 2], acc[c4 * 4 + 3]);
}

// ---------------------------------------------------------------------------
extern "C" void kernel_launch(void* const* d_in, const int* in_sizes, int n_in,
                              void* d_out, int out_size)
{
    const float* feature    = (const float*)d_in[0];
    const float* W1         = (const float*)d_in[1];
    const float* b1         = (const float*)d_in[2];
    const float* W2         = (const float*)d_in[3];
    const float* b2         = (const float*)d_in[4];
    const float* temp       = (const float*)d_in[5];
    const float* norm       = (const float*)d_in[6];
    const int*   edge_index = (const int*)d_in[7];
    float* out = (float*)d_out;

    // CSR build
    zero_count_kernel<<<(NN + 255) / 256, 256>>>();
    hist_kernel<<<(EE + 255) / 256, 256>>>(edge_index);
    scan_kernel<<<1, 1024>>>();
    scatter_kernel<<<(EE + 255) / 256, 256>>>(edge_index, norm);

    // lin1 + relu + hidden init (tensor cores, split-bf16, ldmatrix)
    gemm1_tc_kernel<<<(NN + 127) / 128, 256>>>(feature, W1, b1, temp);

    // K propagation steps (fp16 x with 16^-k rescale)
    int prop_blocks = (NN * 32 + 255) / 256;
    float gs = 1.0f;
    for (int k = 1; k <= KSTEPS; ++k) {
        gs *= 16.0f;
        prop_step_kernel<<<prop_blocks, 256>>>((k - 1) & 1, k, gs, temp);
    }

    // lin2
    gemm2_kernel<<<(NN + 255) / 256, 256>>>(W2, b2, out);
}

// round 4
// speedup vs baseline: 1.6863x; 1.0737x over previous
#include <cuda_runtime.h>
#include <cuda_fp16.h>
#include <cuda_bf16.h>
#include <cstdint>

#define NN    50000
#define EE    800000
#define INF   500
#define HDIM  128
#define CDIM  40
#define KSTEPS 10
#define SCAN_B 1024
#define NBLK ((NN + SCAN_B - 1) / SCAN_B)   // 49

// Scratch (static __device__ allocations, ~180 MB)
__device__ __half g_xbuf[KSTEPS + 1][(size_t)NN * HDIM];  // x_k / 16^k
__device__ float  g_hidden[(size_t)NN * HDIM];
__device__ int    g_rowptr[NN + 1];
__device__ int    g_count[NN];
__device__ int    g_cursor[NN];
__device__ int2   g_edges[EE];    // (src, norm/16 as float bits)
__device__ int    g_bsum[NBLK];
__device__ int    g_boff[NBLK];

// ---------------------------------------------------------------------------
// CSR build
// ---------------------------------------------------------------------------
__global__ void zero_count_kernel() {
    int i = blockIdx.x * blockDim.x + threadIdx.x;
    if (i < NN) g_count[i] = 0;
}

__global__ void hist_kernel(const int* __restrict__ edge_index) {
    int e = blockIdx.x * blockDim.x + threadIdx.x;
    if (e < EE) atomicAdd(&g_count[edge_index[EE + e]], 1);
}

// block-level exclusive scan; block totals to g_bsum
__global__ __launch_bounds__(SCAN_B) void scanA_kernel() {
    __shared__ int wsum[32];
    int i = blockIdx.x * SCAN_B + threadIdx.x;
    int lane = threadIdx.x & 31, wid = threadIdx.x >> 5;
    int v = (i < NN) ? g_count[i] : 0;
    int incl = v;
#pragma unroll
    for (int off = 1; off < 32; off <<= 1) {
        int t = __shfl_up_sync(0xffffffffu, incl, off);
        if (lane >= off) incl += t;
    }
    if (lane == 31) wsum[wid] = incl;
    __syncthreads();
    if (wid == 0) {
        int s = wsum[lane];
        int si = s;
#pragma unroll
        for (int off = 1; off < 32; off <<= 1) {
            int t = __shfl_up_sync(0xffffffffu, si, off);
            if (lane >= off) si += t;
        }
        wsum[lane] = si - s;
    }
    __syncthreads();
    int excl = incl - v + wsum[wid];
    if (i < NN) g_rowptr[i] = excl;
    if (threadIdx.x == SCAN_B - 1) g_bsum[blockIdx.x] = excl + v;
}

// scan the 49 block sums (1 block, 64 threads)
__global__ void scanB_kernel() {
    __shared__ int s[64];
    int t = threadIdx.x;
    int v = (t < NBLK) ? g_bsum[t] : 0;
    s[t] = v;
    __syncthreads();
    for (int off = 1; off < 64; off <<= 1) {
        int val = (t >= off) ? s[t - off] : 0;
        __syncthreads();
        s[t] += val;
        __syncthreads();
    }
    if (t < NBLK) g_boff[t] = s[t] - v;
}

__global__ void scanC_kernel() {
    int i = blockIdx.x * blockDim.x + threadIdx.x;
    if (i < NN) {
        int r = g_rowptr[i] + g_boff[i / SCAN_B];
        g_rowptr[i] = r;
        g_cursor[i] = r;
    }
    if (i == 0) g_rowptr[NN] = EE;
}

__global__ void scatter_kernel(const int* __restrict__ edge_index,
                               const float* __restrict__ norm) {
    int e = blockIdx.x * blockDim.x + threadIdx.x;
    if (e < EE) {
        int s = edge_index[e];
        int d = edge_index[EE + e];
        int pos = atomicAdd(&g_cursor[d], 1);
        g_edges[pos] = make_int2(s, __float_as_int(norm[e] * 0.0625f));
    }
}

// ---------------------------------------------------------------------------
// GEMM1 (tensor cores, split-bf16 3-pass, ldmatrix + STS.64):
//   x0 = relu(feature @ W1 + b1) -> g_xbuf[0] (fp16)
// ---------------------------------------------------------------------------
__device__ __forceinline__ void mma16816(float c[4], const uint32_t a[4],
                                         uint32_t b0, uint32_t b1) {
    asm volatile(
        "mma.sync.aligned.m16n8k16.row.col.f32.bf16.bf16.f32 "
        "{%0,%1,%2,%3}, {%4,%5,%6,%7}, {%8,%9}, {%0,%1,%2,%3};"
        : "+f"(c[0]), "+f"(c[1]), "+f"(c[2]), "+f"(c[3])
        : "r"(a[0]), "r"(a[1]), "r"(a[2]), "r"(a[3]), "r"(b0), "r"(b1));
}

__device__ __forceinline__ void ldsm4(uint32_t& r0, uint32_t& r1,
                                      uint32_t& r2, uint32_t& r3, uint32_t addr) {
    asm volatile(
        "ldmatrix.sync.aligned.m8n8.x4.shared.b16 {%0,%1,%2,%3}, [%4];"
        : "=r"(r0), "=r"(r1), "=r"(r2), "=r"(r3) : "r"(addr));
}

__device__ __forceinline__ void split_bf16(float v, __nv_bfloat16& hi, __nv_bfloat16& lo) {
    hi = __float2bfloat16_rn(v);
    lo = __float2bfloat16_rn(v - __bfloat162float(hi));
}

#define PADC 40   // smem row length in bf16 (80 bytes) — LDSM conflict-free

__global__ __launch_bounds__(256) void gemm1_tc_kernel(
    const float* __restrict__ A,     // [NN, INF]
    const float* __restrict__ B,     // [INF, HDIM]
    const float* __restrict__ b1)    // [HDIM]
{
    __shared__ __nv_bfloat16 Ah[128][PADC];
    __shared__ __nv_bfloat16 Al[128][PADC];
    __shared__ __nv_bfloat16 Bh[128][PADC];   // transposed: [n][k]
    __shared__ __nv_bfloat16 Bl[128][PADC];
    __shared__ float sBias[HDIM];

    int tid = threadIdx.x;
    int m0 = blockIdx.x * 128;

    if (tid < HDIM) sBias[tid] = b1[tid];

    int lane = tid & 31, wid = tid >> 5;
    int g = lane >> 2, tig = lane & 3;
    int wr = wid >> 1, wc = wid & 1;
    int mBase = wr * 32, nBase = wc * 64;

    uint32_t ahBase = (uint32_t)__cvta_generic_to_shared(&Ah[0][0]);
    uint32_t alBase = (uint32_t)__cvta_generic_to_shared(&Al[0][0]);
    uint32_t bhBase = (uint32_t)__cvta_generic_to_shared(&Bh[0][0]);
    uint32_t blBase = (uint32_t)__cvta_generic_to_shared(&Bl[0][0]);

    int aRow = mBase + (lane & 7) + ((lane >> 3) & 1) * 8;
    uint32_t aOff = (uint32_t)(aRow * (PADC * 2) + ((lane >> 4) & 1) * 16);
    int bRow = nBase + (lane & 7) + ((lane >> 4) & 1) * 8;
    uint32_t bOff = (uint32_t)(bRow * (PADC * 2) + ((lane >> 3) & 1) * 16);

    float c[2][8][4];
#pragma unroll
    for (int mt = 0; mt < 2; ++mt)
#pragma unroll
        for (int nt = 0; nt < 8; ++nt)
#pragma unroll
            for (int q = 0; q < 4; ++q) c[mt][nt][q] = 0.f;

    for (int k0 = 0; k0 < 512; k0 += 32) {
#pragma unroll
        for (int i = 0; i < 4; ++i) {
            int idx = tid + 256 * i;
            int row = idx >> 3;
            int c4  = (idx & 7) * 4;
            int grow = m0 + row;
            int gk = k0 + c4;
            float4 v = make_float4(0.f, 0.f, 0.f, 0.f);
            if (grow < NN && gk + 4 <= INF)
                v = *(const float4*)(A + (size_t)grow * INF + gk);
            __nv_bfloat16 h[4], l[4];
            split_bf16(v.x, h[0], l[0]);
            split_bf16(v.y, h[1], l[1]);
            split_bf16(v.z, h[2], l[2]);
            split_bf16(v.w, h[3], l[3]);
            *(uint2*)&Ah[row][c4] = *(uint2*)h;
            *(uint2*)&Al[row][c4] = *(uint2*)l;
        }
#pragma unroll
        for (int i = 0; i < 4; ++i) {
            int idx = tid + 256 * i;
            int n    = idx & 127;
            int kr4  = (idx >> 7) * 4;
            __nv_bfloat16 h[4], l[4];
#pragma unroll
            for (int j = 0; j < 4; ++j) {
                int gk = k0 + kr4 + j;
                float v = (gk < INF) ? __ldg(B + (size_t)gk * HDIM + n) : 0.f;
                split_bf16(v, h[j], l[j]);
            }
            *(uint2*)&Bh[n][kr4] = *(uint2*)h;
            *(uint2*)&Bl[n][kr4] = *(uint2*)l;
        }
        __syncthreads();

#pragma unroll
        for (int kk = 0; kk < 32; kk += 16) {
            uint32_t AH[2][4], AL[2][4];
#pragma unroll
            for (int mt = 0; mt < 2; ++mt) {
                uint32_t off = aOff + (uint32_t)(mt * 16 * PADC * 2 + kk * 2);
                ldsm4(AH[mt][0], AH[mt][1], AH[mt][2], AH[mt][3], ahBase + off);
                ldsm4(AL[mt][0], AL[mt][1], AL[mt][2], AL[mt][3], alBase + off);
            }
#pragma unroll
            for (int np = 0; np < 4; ++np) {
                uint32_t off = bOff + (uint32_t)(np * 16 * PADC * 2 + kk * 2);
                uint32_t BH[4], BL[4];
                ldsm4(BH[0], BH[1], BH[2], BH[3], bhBase + off);
                ldsm4(BL[0], BL[1], BL[2], BL[3], blBase + off);
#pragma unroll
                for (int mt = 0; mt < 2; ++mt) {
                    mma16816(c[mt][2 * np],     AH[mt], BH[0], BH[1]);
                    mma16816(c[mt][2 * np],     AH[mt], BL[0], BL[1]);
                    mma16816(c[mt][2 * np],     AL[mt], BH[0], BH[1]);
                    mma16816(c[mt][2 * np + 1], AH[mt], BH[2], BH[3]);
                    mma16816(c[mt][2 * np + 1], AH[mt], BL[2], BL[3]);
                    mma16816(c[mt][2 * np + 1], AL[mt], BH[2], BH[3]);
                }
            }
        }
        __syncthreads();
    }

    // epilogue: bias+relu -> fp16 x0
#pragma unroll
    for (int mt = 0; mt < 2; ++mt) {
#pragma unroll
        for (int nt = 0; nt < 8; ++nt) {
            int col = nBase + nt * 8 + 2 * tig;
            float bb0 = sBias[col], bb1 = sBias[col + 1];
#pragma unroll
            for (int rh = 0; rh < 2; ++rh) {
                int row = m0 + mBase + mt * 16 + g + rh * 8;
                if (row >= NN) continue;
                float v0 = fmaxf(c[mt][nt][rh * 2 + 0] + bb0, 0.f);
                float v1 = fmaxf(c[mt][nt][rh * 2 + 1] + bb1, 0.f);
                *(__half2*)(&g_xbuf[0][(size_t)row * HDIM + col]) =
                    __floats2half2_rn(v0, v1);
            }
        }
    }
}

// ---------------------------------------------------------------------------
// Propagation step k: g_xbuf[k][n] = sum_e norm16[e] * g_xbuf[k-1][src[e]]
// Warp per node; half-warp per edge; lane = 8 channels (uint4 of fp16).
// ---------------------------------------------------------------------------
__global__ __launch_bounds__(256) void prop_step_kernel(int k)
{
    const __half* __restrict__ xin  = g_xbuf[k - 1];
    __half* __restrict__       xout = g_xbuf[k];

    int w    = (blockIdx.x * blockDim.x + threadIdx.x) >> 5;
    int lane = threadIdx.x & 31;
    if (w >= NN) return;

    int beg = g_rowptr[w];
    int deg = g_rowptr[w + 1] - beg;
    int h  = lane >> 4;       // which edge of the pair
    int cg = lane & 15;       // channel group (8 ch)

    float a0 = 0.f, a1 = 0.f, a2 = 0.f, a3 = 0.f;
    float a4 = 0.f, a5 = 0.f, a6 = 0.f, a7 = 0.f;
    const uint4* xin16 = (const uint4*)xin;

#pragma unroll 4
    for (int e = h; e < deg; e += 2) {
        int2 md = __ldg(&g_edges[beg + e]);
        float ww = __int_as_float(md.y);
        uint4 u = __ldg(xin16 + ((size_t)md.x * 16 + cg));
        float2 f0 = __half22float2(*(__half2*)&u.x);
        float2 f1 = __half22float2(*(__half2*)&u.y);
        float2 f2 = __half22float2(*(__half2*)&u.z);
        float2 f3 = __half22float2(*(__half2*)&u.w);
        a0 += ww * f0.x;  a1 += ww * f0.y;
        a2 += ww * f1.x;  a3 += ww * f1.y;
        a4 += ww * f2.x;  a5 += ww * f2.y;
        a6 += ww * f3.x;  a7 += ww * f3.y;
    }

    // merge the two half-warps (same channels, different edges)
    a0 += __shfl_xor_sync(0xffffffffu, a0, 16);
    a1 += __shfl_xor_sync(0xffffffffu, a1, 16);
    a2 += __shfl_xor_sync(0xffffffffu, a2, 16);
    a3 += __shfl_xor_sync(0xffffffffu, a3, 16);
    a4 += __shfl_xor_sync(0xffffffffu, a4, 16);
    a5 += __shfl_xor_sync(0xffffffffu, a5, 16);
    a6 += __shfl_xor_sync(0xffffffffu, a6, 16);
    a7 += __shfl_xor_sync(0xffffffffu, a7, 16);

    if (h == 0) {
        uint4 o;
        *(__half2*)&o.x = __floats2half2_rn(a0, a1);
        *(__half2*)&o.y = __floats2half2_rn(a2, a3);
        *(__half2*)&o.z = __floats2half2_rn(a4, a5);
        *(__half2*)&o.w = __floats2half2_rn(a6, a7);
        ((uint4*)xout)[(size_t)w * 16 + cg] = o;
    }
}

// ---------------------------------------------------------------------------
// Combine: hidden[n,c] = sum_k temp[c,k] * 16^k * g_xbuf[k][n,c]
// Thread = (node, 8-channel group); grid-stride keeps cg fixed per thread.
// ---------------------------------------------------------------------------
__global__ __launch_bounds__(256) void combine_kernel(const float* __restrict__ temp)
{
    __shared__ float sG[HDIM][KSTEPS + 1];
    int t = threadIdx.x;
    for (int idx = t; idx < HDIM * (KSTEPS + 1); idx += 256) {
        int c = idx / (KSTEPS + 1), k = idx % (KSTEPS + 1);
        sG[c][k] = temp[idx] * ldexpf(1.f, 4 * k);   // * 16^k
    }
    __syncthreads();

    int cg = t & 15;
    float G[8][KSTEPS + 1];
#pragma unroll
    for (int j = 0; j < 8; ++j)
#pragma unroll
        for (int k = 0; k <= KSTEPS; ++k)
            G[j][k] = sG[cg * 8 + j][k];

    int stride = gridDim.x * blockDim.x;   // multiple of 16
    for (int idx = blockIdx.x * 256 + t; idx < NN * 16; idx += stride) {
        int n = idx >> 4;                  // idx & 15 == cg
        float acc[8] = {0.f, 0.f, 0.f, 0.f, 0.f, 0.f, 0.f, 0.f};
#pragma unroll
        for (int k = 0; k <= KSTEPS; ++k) {
            uint4 u = __ldg((const uint4*)&g_xbuf[k][0] + ((size_t)n * 16 + cg));
            float2 f0 = __half22float2(*(__half2*)&u.x);
            float2 f1 = __half22float2(*(__half2*)&u.y);
            float2 f2 = __half22float2(*(__half2*)&u.z);
            float2 f3 = __half22float2(*(__half2*)&u.w);
            acc[0] += G[0][k] * f0.x;  acc[1] += G[1][k] * f0.y;
            acc[2] += G[2][k] * f1.x;  acc[3] += G[3][k] * f1.y;
            acc[4] += G[4][k] * f2.x;  acc[5] += G[5][k] * f2.y;
            acc[6] += G[6][k] * f3.x;  acc[7] += G[7][k] * f3.y;
        }
        float4* o = (float4*)(g_hidden + (size_t)n * HDIM + cg * 8);
        o[0] = make_float4(acc[0], acc[1], acc[2], acc[3]);
        o[1] = make_float4(acc[4], acc[5], acc[6], acc[7]);
    }
}

// ---------------------------------------------------------------------------
// GEMM2: out = hidden @ W2 + b2   (thread per node, acc[40] in registers)
// ---------------------------------------------------------------------------
__global__ __launch_bounds__(256) void gemm2_kernel(
    const float* __restrict__ W2,   // [HDIM, CDIM]
    const float* __restrict__ b2,   // [CDIM]
    float* __restrict__ out)        // [NN, CDIM]
{
    __shared__ float sW[HDIM * CDIM];
    __shared__ float sb[CDIM];
    for (int i = threadIdx.x; i < HDIM * CDIM; i += blockDim.x) sW[i] = W2[i];
    if (threadIdx.x < CDIM) sb[threadIdx.x] = b2[threadIdx.x];
    __syncthreads();

    int n = blockIdx.x * blockDim.x + threadIdx.x;
    if (n >= NN) return;

    float acc[CDIM];
#pragma unroll
    for (int c = 0; c < CDIM; ++c) acc[c] = sb[c];

    const float4* hrow = (const float4*)(g_hidden + (size_t)n * HDIM);
#pragma unroll 4
    for (int h4 = 0; h4 < HDIM / 4; ++h4) {
        float4 hv = __ldg(hrow + h4);
        const float* w0 = &sW[(h4 * 4 + 0) * CDIM];
        const float* w1 = &sW[(h4 * 4 + 1) * CDIM];
        const float* w2 = &sW[(h4 * 4 + 2) * CDIM];
        const float* w3 = &sW[(h4 * 4 + 3) * CDIM];
#pragma unroll
        for (int c = 0; c < CDIM; ++c) {
            acc[c] += hv.x * w0[c];
            acc[c] += hv.y * w1[c];
            acc[c] += hv.z * w2[c];
            acc[c] += hv.w * w3[c];
        }
    }

    float4* o = (float4*)(out + (size_t)n * CDIM);
#pragma unroll
    for (int c4 = 0; c4 < CDIM / 4; ++c4)
        o[c4] = make_float4(acc[c4 * 4], acc[c4 * 4 + 1], acc[c4 * 4 + 2], acc[c4 * 4 + 3]);
}

// ---------------------------------------------------------------------------
extern "C" void kernel_launch(void* const* d_in, const int* in_sizes, int n_in,
                              void* d_out, int out_size)
{
    const float* feature    = (const float*)d_in[0];
    const float* W1         = (const float*)d_in[1];
    const float* b1         = (const float*)d_in[2];
    const float* W2         = (const float*)d_in[3];
    const float* b2         = (const float*)d_in[4];
    const float* temp       = (const float*)d_in[5];
    const float* norm       = (const float*)d_in[6];
    const int*   edge_index = (const int*)d_in[7];
    float* out = (float*)d_out;

    // CSR build
    zero_count_kernel<<<(NN + 255) / 256, 256>>>();
    hist_kernel<<<(EE + 255) / 256, 256>>>(edge_index);
    scanA_kernel<<<NBLK, SCAN_B>>>();
    scanB_kernel<<<1, 64>>>();
    scanC_kernel<<<(NN + 255) / 256, 256>>>();
    scatter_kernel<<<(EE + 255) / 256, 256>>>(edge_index, norm);

    // lin1 + relu (tensor cores, split-bf16)
    gemm1_tc_kernel<<<(NN + 127) / 128, 256>>>(feature, W1, b1);

    // K propagation steps (fp16 x with 16^-k rescale), hidden deferred
    int prop_blocks = (NN * 32 + 255) / 256;
    for (int k = 1; k <= KSTEPS; ++k)
        prop_step_kernel<<<prop_blocks, 256>>>(k);

    // hidden = sum_k gamma_k 16^k x_k
    combine_kernel<<<256, 256>>>(temp);

    // lin2
    gemm2_kernel<<<(NN + 255) / 256, 256>>>(W2, b2, out);
}

// round 5
// speedup vs baseline: 1.7682x; 1.0486x over previous
#include <cuda_runtime.h>
#include <cuda_fp16.h>
#include <cuda_bf16.h>
#include <cstdint>

#define NN    50000
#define EE    800000
#define INF   500
#define HDIM  128
#define CDIM  40
#define KSTEPS 10
#define SCAN_B 1024
#define NBLK ((NN + SCAN_B - 1) / SCAN_B)   // 49
#define KPAD 512

// Scratch (static __device__ allocations)
__device__ __half g_xbuf[KSTEPS + 1][(size_t)NN * HDIM];  // x_k / 16^k
__device__ float  g_hidden[(size_t)NN * HDIM];
__device__ int    g_rowptr[NN + 1];
__device__ int    g_count[NN];
__device__ int    g_cursor[NN];
__device__ int2   g_edges[EE];    // (src, norm/16 as float bits)
__device__ int    g_bsum[NBLK];
__device__ int    g_boff[NBLK];
__device__ __nv_bfloat16 g_w1h[HDIM * KPAD];  // W1^T hi, [n][k]
__device__ __nv_bfloat16 g_w1l[HDIM * KPAD];  // W1^T lo

// ---------------------------------------------------------------------------
// CSR build
// ---------------------------------------------------------------------------
__global__ void zero_count_kernel() {
    int i = blockIdx.x * blockDim.x + threadIdx.x;
    if (i < NN) g_count[i] = 0;
}

__global__ void hist_kernel(const int* __restrict__ edge_index) {
    int e = blockIdx.x * blockDim.x + threadIdx.x;
    if (e < EE) atomicAdd(&g_count[edge_index[EE + e]], 1);
}

__global__ __launch_bounds__(SCAN_B) void scanA_kernel() {
    __shared__ int wsum[32];
    int i = blockIdx.x * SCAN_B + threadIdx.x;
    int lane = threadIdx.x & 31, wid = threadIdx.x >> 5;
    int v = (i < NN) ? g_count[i] : 0;
    int incl = v;
#pragma unroll
    for (int off = 1; off < 32; off <<= 1) {
        int t = __shfl_up_sync(0xffffffffu, incl, off);
        if (lane >= off) incl += t;
    }
    if (lane == 31) wsum[wid] = incl;
    __syncthreads();
    if (wid == 0) {
        int s = wsum[lane];
        int si = s;
#pragma unroll
        for (int off = 1; off < 32; off <<= 1) {
            int t = __shfl_up_sync(0xffffffffu, si, off);
            if (lane >= off) si += t;
        }
        wsum[lane] = si - s;
    }
    __syncthreads();
    int excl = incl - v + wsum[wid];
    if (i < NN) g_rowptr[i] = excl;
    if (threadIdx.x == SCAN_B - 1) g_bsum[blockIdx.x] = excl + v;
}

__global__ void scanB_kernel() {
    __shared__ int s[64];
    int t = threadIdx.x;
    int v = (t < NBLK) ? g_bsum[t] : 0;
    s[t] = v;
    __syncthreads();
    for (int off = 1; off < 64; off <<= 1) {
        int val = (t >= off) ? s[t - off] : 0;
        __syncthreads();
        s[t] += val;
        __syncthreads();
    }
    if (t < NBLK) g_boff[t] = s[t] - v;
}

__global__ void scanC_kernel() {
    int i = blockIdx.x * blockDim.x + threadIdx.x;
    if (i < NN) {
        int r = g_rowptr[i] + g_boff[i / SCAN_B];
        g_rowptr[i] = r;
        g_cursor[i] = r;
    }
    if (i == 0) g_rowptr[NN] = EE;
}

__global__ void scatter_kernel(const int* __restrict__ edge_index,
                               const float* __restrict__ norm) {
    int e = blockIdx.x * blockDim.x + threadIdx.x;
    if (e < EE) {
        int s = edge_index[e];
        int d = edge_index[EE + e];
        int pos = atomicAdd(&g_cursor[d], 1);
        g_edges[pos] = make_int2(s, __float_as_int(norm[e] * 0.0625f));
    }
}

// ---------------------------------------------------------------------------
// W1 preconvert: split-bf16, transposed [n][k], k padded to 512 with zeros
// ---------------------------------------------------------------------------
__device__ __forceinline__ void split_bf16(float v, __nv_bfloat16& hi, __nv_bfloat16& lo) {
    hi = __float2bfloat16_rn(v);
    lo = __float2bfloat16_rn(v - __bfloat162float(hi));
}

__global__ void conv_w1_kernel(const float* __restrict__ W1) {  // [INF][HDIM]
    int idx = blockIdx.x * 256 + threadIdx.x;   // over HDIM*KPAD
    if (idx >= HDIM * KPAD) return;
    int n = idx / KPAD, k = idx % KPAD;
    __nv_bfloat16 hi = __float2bfloat16_rn(0.f), lo = hi;
    if (k < INF) split_bf16(W1[(size_t)k * HDIM + n], hi, lo);
    g_w1h[idx] = hi;
    g_w1l[idx] = lo;
}

// ---------------------------------------------------------------------------
// GEMM1 (tensor cores, split-bf16 3-pass, ldmatrix; B copied preconverted):
//   x0 = relu(feature @ W1 + b1) -> g_xbuf[0] (fp16)
// ---------------------------------------------------------------------------
__device__ __forceinline__ void mma16816(float c[4], const uint32_t a[4],
                                         uint32_t b0, uint32_t b1) {
    asm volatile(
        "mma.sync.aligned.m16n8k16.row.col.f32.bf16.bf16.f32 "
        "{%0,%1,%2,%3}, {%4,%5,%6,%7}, {%8,%9}, {%0,%1,%2,%3};"
        : "+f"(c[0]), "+f"(c[1]), "+f"(c[2]), "+f"(c[3])
        : "r"(a[0]), "r"(a[1]), "r"(a[2]), "r"(a[3]), "r"(b0), "r"(b1));
}

__device__ __forceinline__ void ldsm4(uint32_t& r0, uint32_t& r1,
                                      uint32_t& r2, uint32_t& r3, uint32_t addr) {
    asm volatile(
        "ldmatrix.sync.aligned.m8n8.x4.shared.b16 {%0,%1,%2,%3}, [%4];"
        : "=r"(r0), "=r"(r1), "=r"(r2), "=r"(r3) : "r"(addr));
}

#define PADC 40   // smem row length in bf16 (80 bytes) — LDSM conflict-free

__global__ __launch_bounds__(256) void gemm1_tc_kernel(
    const float* __restrict__ A,     // [NN, INF]
    const float* __restrict__ b1)    // [HDIM]
{
    __shared__ __nv_bfloat16 Ah[128][PADC];
    __shared__ __nv_bfloat16 Al[128][PADC];
    __shared__ __nv_bfloat16 Bh[128][PADC];   // transposed: [n][k]
    __shared__ __nv_bfloat16 Bl[128][PADC];
    __shared__ float sBias[HDIM];

    int tid = threadIdx.x;
    int m0 = blockIdx.x * 128;

    if (tid < HDIM) sBias[tid] = b1[tid];

    int lane = tid & 31, wid = tid >> 5;
    int g = lane >> 2, tig = lane & 3;
    int wr = wid >> 1, wc = wid & 1;
    int mBase = wr * 32, nBase = wc * 64;

    uint32_t ahBase = (uint32_t)__cvta_generic_to_shared(&Ah[0][0]);
    uint32_t alBase = (uint32_t)__cvta_generic_to_shared(&Al[0][0]);
    uint32_t bhBase = (uint32_t)__cvta_generic_to_shared(&Bh[0][0]);
    uint32_t blBase = (uint32_t)__cvta_generic_to_shared(&Bl[0][0]);

    int aRow = mBase + (lane & 7) + ((lane >> 3) & 1) * 8;
    uint32_t aOff = (uint32_t)(aRow * (PADC * 2) + ((lane >> 4) & 1) * 16);
    int bRow = nBase + (lane & 7) + ((lane >> 4) & 1) * 8;
    uint32_t bOff = (uint32_t)(bRow * (PADC * 2) + ((lane >> 3) & 1) * 16);

    float c[2][8][4];
#pragma unroll
    for (int mt = 0; mt < 2; ++mt)
#pragma unroll
        for (int nt = 0; nt < 8; ++nt)
#pragma unroll
            for (int q = 0; q < 4; ++q) c[mt][nt][q] = 0.f;

    for (int k0 = 0; k0 < 512; k0 += 32) {
        // ---- A tile: 128x32 fp32 -> split bf16, STS.64 ----
#pragma unroll
        for (int i = 0; i < 4; ++i) {
            int idx = tid + 256 * i;
            int row = idx >> 3;
            int c4  = (idx & 7) * 4;
            int grow = m0 + row;
            int gk = k0 + c4;
            float4 v = make_float4(0.f, 0.f, 0.f, 0.f);
            if (grow < NN && gk + 4 <= INF)
                v = *(const float4*)(A + (size_t)grow * INF + gk);
            __nv_bfloat16 h[4], l[4];
            split_bf16(v.x, h[0], l[0]);
            split_bf16(v.y, h[1], l[1]);
            split_bf16(v.z, h[2], l[2]);
            split_bf16(v.w, h[3], l[3]);
            *(uint2*)&Ah[row][c4] = *(uint2*)h;
            *(uint2*)&Al[row][c4] = *(uint2*)l;
        }
        // ---- B tile: pure copy of preconverted W1^T (128x32 bf16) ----
#pragma unroll
        for (int i = 0; i < 2; ++i) {
            int idx = tid + 256 * i;       // 512 uint4 slots
            int n   = idx >> 2;
            int kr8 = (idx & 3) * 8;
            *(uint4*)&Bh[n][kr8] = *(const uint4*)&g_w1h[n * KPAD + k0 + kr8];
            *(uint4*)&Bl[n][kr8] = *(const uint4*)&g_w1l[n * KPAD + k0 + kr8];
        }
        __syncthreads();

#pragma unroll
        for (int kk = 0; kk < 32; kk += 16) {
            uint32_t AH[2][4], AL[2][4];
#pragma unroll
            for (int mt = 0; mt < 2; ++mt) {
                uint32_t off = aOff + (uint32_t)(mt * 16 * PADC * 2 + kk * 2);
                ldsm4(AH[mt][0], AH[mt][1], AH[mt][2], AH[mt][3], ahBase + off);
                ldsm4(AL[mt][0], AL[mt][1], AL[mt][2], AL[mt][3], alBase + off);
            }
#pragma unroll
            for (int np = 0; np < 4; ++np) {
                uint32_t off = bOff + (uint32_t)(np * 16 * PADC * 2 + kk * 2);
                uint32_t BH[4], BL[4];
                ldsm4(BH[0], BH[1], BH[2], BH[3], bhBase + off);
                ldsm4(BL[0], BL[1], BL[2], BL[3], blBase + off);
#pragma unroll
                for (int mt = 0; mt < 2; ++mt) {
                    mma16816(c[mt][2 * np],     AH[mt], BH[0], BH[1]);
                    mma16816(c[mt][2 * np],     AH[mt], BL[0], BL[1]);
                    mma16816(c[mt][2 * np],     AL[mt], BH[0], BH[1]);
                    mma16816(c[mt][2 * np + 1], AH[mt], BH[2], BH[3]);
                    mma16816(c[mt][2 * np + 1], AH[mt], BL[2], BL[3]);
                    mma16816(c[mt][2 * np + 1], AL[mt], BH[2], BH[3]);
                }
            }
        }
        __syncthreads();
    }

    // epilogue: bias+relu -> fp16 x0
#pragma unroll
    for (int mt = 0; mt < 2; ++mt) {
#pragma unroll
        for (int nt = 0; nt < 8; ++nt) {
            int col = nBase + nt * 8 + 2 * tig;
            float bb0 = sBias[col], bb1 = sBias[col + 1];
#pragma unroll
            for (int rh = 0; rh < 2; ++rh) {
                int row = m0 + mBase + mt * 16 + g + rh * 8;
                if (row >= NN) continue;
                float v0 = fmaxf(c[mt][nt][rh * 2 + 0] + bb0, 0.f);
                float v1 = fmaxf(c[mt][nt][rh * 2 + 1] + bb1, 0.f);
                *(__half2*)(&g_xbuf[0][(size_t)row * HDIM + col]) =
                    __floats2half2_rn(v0, v1);
            }
        }
    }
}

// ---------------------------------------------------------------------------
// Propagation step k: half-warp (16 lanes) per node; lane = 8 channels (uint4)
// ---------------------------------------------------------------------------
__global__ __launch_bounds__(256) void prop_step_kernel(int k)
{
    const __half* __restrict__ xin  = g_xbuf[k - 1];
    __half* __restrict__       xout = g_xbuf[k];

    int hw = (blockIdx.x * blockDim.x + threadIdx.x) >> 4;   // node
    int cg = threadIdx.x & 15;                               // channel group
    if (hw >= NN) return;

    int beg = g_rowptr[hw];
    int end = g_rowptr[hw + 1];

    float a0 = 0.f, a1 = 0.f, a2 = 0.f, a3 = 0.f;
    float a4 = 0.f, a5 = 0.f, a6 = 0.f, a7 = 0.f;
    const uint4* xin16 = (const uint4*)xin;

#pragma unroll 4
    for (int e = beg; e < end; ++e) {
        int2 md = __ldg(&g_edges[e]);        // broadcast within half-warp
        float ww = __int_as_float(md.y);
        uint4 u = __ldg(xin16 + ((size_t)md.x * 16 + cg));
        float2 f0 = __half22float2(*(__half2*)&u.x);
        float2 f1 = __half22float2(*(__half2*)&u.y);
        float2 f2 = __half22float2(*(__half2*)&u.z);
        float2 f3 = __half22float2(*(__half2*)&u.w);
        a0 += ww * f0.x;  a1 += ww * f0.y;
        a2 += ww * f1.x;  a3 += ww * f1.y;
        a4 += ww * f2.x;  a5 += ww * f2.y;
        a6 += ww * f3.x;  a7 += ww * f3.y;
    }

    uint4 o;
    *(__half2*)&o.x = __floats2half2_rn(a0, a1);
    *(__half2*)&o.y = __floats2half2_rn(a2, a3);
    *(__half2*)&o.z = __floats2half2_rn(a4, a5);
    *(__half2*)&o.w = __floats2half2_rn(a6, a7);
    ((uint4*)xout)[(size_t)hw * 16 + cg] = o;
}

// ---------------------------------------------------------------------------
// Combine: hidden[n,c] = sum_k temp[c,k] * 16^k * g_xbuf[k][n,c]
// ---------------------------------------------------------------------------
__global__ __launch_bounds__(256) void combine_kernel(const float* __restrict__ temp)
{
    __shared__ float sG[HDIM][KSTEPS + 1];
    int t = threadIdx.x;
    for (int idx = t; idx < HDIM * (KSTEPS + 1); idx += 256) {
        int c = idx / (KSTEPS + 1), k = idx % (KSTEPS + 1);
        sG[c][k] = temp[idx] * (float)(1u << (2 * k)) * (float)(1u << (2 * k));  // 16^k
    }
    __syncthreads();

    int cg = t & 15;
    float G[8][KSTEPS + 1];
#pragma unroll
    for (int j = 0; j < 8; ++j)
#pragma unroll
        for (int k = 0; k <= KSTEPS; ++k)
            G[j][k] = sG[cg * 8 + j][k];

    int stride = gridDim.x * blockDim.x;
    for (int idx = blockIdx.x * 256 + t; idx < NN * 16; idx += stride) {
        int n = idx >> 4;
        float acc[8] = {0.f, 0.f, 0.f, 0.f, 0.f, 0.f, 0.f, 0.f};
#pragma unroll
        for (int k = 0; k <= KSTEPS; ++k) {
            uint4 u = __ldg((const uint4*)&g_xbuf[k][0] + ((size_t)n * 16 + cg));
            float2 f0 = __half22float2(*(__half2*)&u.x);
            float2 f1 = __half22float2(*(__half2*)&u.y);
            float2 f2 = __half22float2(*(__half2*)&u.z);
            float2 f3 = __half22float2(*(__half2*)&u.w);
            acc[0] += G[0][k] * f0.x;  acc[1] += G[1][k] * f0.y;
            acc[2] += G[2][k] * f1.x;  acc[3] += G[3][k] * f1.y;
            acc[4] += G[4][k] * f2.x;  acc[5] += G[5][k] * f2.y;
            acc[6] += G[6][k] * f3.x;  acc[7] += G[7][k] * f3.y;
        }
        float4* o = (float4*)(g_hidden + (size_t)n * HDIM + cg * 8);
        o[0] = make_float4(acc[0], acc[1], acc[2], acc[3]);
        o[1] = make_float4(acc[4], acc[5], acc[6], acc[7]);
    }
}

// ---------------------------------------------------------------------------
// GEMM2: out = hidden @ W2 + b2   (thread per node, acc[40] in registers)
// ---------------------------------------------------------------------------
__global__ __launch_bounds__(256) void gemm2_kernel(
    const float* __restrict__ W2,   // [HDIM, CDIM]
    const float* __restrict__ b2,   // [CDIM]
    float* __restrict__ out)        // [NN, CDIM]
{
    __shared__ float sW[HDIM * CDIM];
    __shared__ float sb[CDIM];
    for (int i = threadIdx.x; i < HDIM * CDIM; i += blockDim.x) sW[i] = W2[i];
    if (threadIdx.x < CDIM) sb[threadIdx.x] = b2[threadIdx.x];
    __syncthreads();

    int n = blockIdx.x * blockDim.x + threadIdx.x;
    if (n >= NN) return;

    float acc[CDIM];
#pragma unroll
    for (int c = 0; c < CDIM; ++c) acc[c] = sb[c];

    const float4* hrow = (const float4*)(g_hidden + (size_t)n * HDIM);
#pragma unroll 4
    for (int h4 = 0; h4 < HDIM / 4; ++h4) {
        float4 hv = __ldg(hrow + h4);
        const float* w0 = &sW[(h4 * 4 + 0) * CDIM];
        const float* w1 = &sW[(h4 * 4 + 1) * CDIM];
        const float* w2 = &sW[(h4 * 4 + 2) * CDIM];
        const float* w3 = &sW[(h4 * 4 + 3) * CDIM];
#pragma unroll
        for (int c = 0; c < CDIM; ++c) {
            acc[c] += hv.x * w0[c];
            acc[c] += hv.y * w1[c];
            acc[c] += hv.z * w2[c];
            acc[c] += hv.w * w3[c];
        }
    }

    float4* o = (float4*)(out + (size_t)n * CDIM);
#pragma unroll
    for (int c4 = 0; c4 < CDIM / 4; ++c4)
        o[c4] = make_float4(acc[c4 * 4], acc[c4 * 4 + 1], acc[c4 * 4 + 2], acc[c4 * 4 + 3]);
}

// ---------------------------------------------------------------------------
extern "C" void kernel_launch(void* const* d_in, const int* in_sizes, int n_in,
                              void* d_out, int out_size)
{
    const float* feature    = (const float*)d_in[0];
    const float* W1         = (const float*)d_in[1];
    const float* b1         = (const float*)d_in[2];
    const float* W2         = (const float*)d_in[3];
    const float* b2         = (const float*)d_in[4];
    const float* temp       = (const float*)d_in[5];
    const float* norm       = (const float*)d_in[6];
    const int*   edge_index = (const int*)d_in[7];
    float* out = (float*)d_out;

    // CSR build + W1 preconvert
    zero_count_kernel<<<(NN + 255) / 256, 256>>>();
    conv_w1_kernel<<<(HDIM * KPAD + 255) / 256, 256>>>(W1);
    hist_kernel<<<(EE + 255) / 256, 256>>>(edge_index);
    scanA_kernel<<<NBLK, SCAN_B>>>();
    scanB_kernel<<<1, 64>>>();
    scanC_kernel<<<(NN + 255) / 256, 256>>>();
    scatter_kernel<<<(EE + 255) / 256, 256>>>(edge_index, norm);

    // lin1 + relu (tensor cores, split-bf16)
    gemm1_tc_kernel<<<(NN + 127) / 128, 256>>>(feature, b1);

    // K propagation steps (fp16 x with 16^-k rescale), half-warp per node
    int prop_blocks = (NN * 16 + 255) / 256;
    for (int k = 1; k <= KSTEPS; ++k)
        prop_step_kernel<<<prop_blocks, 256>>>(k);

    // hidden = sum_k gamma_k 16^k x_k
    combine_kernel<<<256, 256>>>(temp);

    // lin2
    gemm2_kernel<<<(NN + 255) / 256, 256>>>(W2, b2, out);
}